// round 13
// baseline (speedup 1.0000x reference)
#include <cuda_runtime.h>
#include <cuda_fp16.h>
#include <cstdint>

#define N_NODES 50000
#define HID 128
#define LATENT 64
#define N_GRAPHS 256
#define BN_EPS 1e-5f
#define SCAN_BLOCKS 196          // 196*256 >= 50000
#define M_TILES 391              // ceil(50000/128)

#define A_PITCH 20               // uints per A smem row -> ldmatrix conflict-free
#define B_PITCH 20               // uints per B^T smem row -> ldmatrix conflict-free

// dynamic smem layout per buffer (bytes)
#define SM_AHI 0
#define SM_ALO 10240             // 128*20*4
#define SM_BHI 20480
#define SM_BLO 30720
#define SM_BUF 40960
#define SM_TOTAL (2 * SM_BUF)

#define W_ELEMS (3 * 128 * 128)  // fused weight image elements (uint-packed, B^T [n][k2])

// ---------------- device scratch (static, no allocation) ----------------
__device__ float g_hf32[N_NODES * HID];           // fp32 h (layer 2 only, for pool)
__device__ int   g_deg[N_NODES];
__device__ int   g_rowstart[N_NODES + 1];
__device__ int   g_cursor[N_NODES];
__device__ int   g_csr[800000 * 2];
__device__ int   g_blocksum[SCAN_BLOCKS];
__device__ float g_pooled[N_GRAPHS * HID];
__device__ float g_scale[HID];
__device__ float g_shift[HID];
// fp16x2-packed hi/lo images (64 uints per 128-ch row)
__device__ unsigned int g_gahi[N_NODES * 64];     // mean of neighbors
__device__ unsigned int g_galo[N_NODES * 64];
__device__ unsigned int g_Ah[2][N_NODES * 64];    // hin ping-pong (x -> buf 0)
__device__ unsigned int g_Al[2][N_NODES * 64];
__device__ unsigned int g_Bhi[W_ELEMS];           // per-layer B^T: [n 128][k2 128]
__device__ unsigned int g_Blo[W_ELEMS];
// grid barrier state (generation counter: robust across launches)
__device__ unsigned g_bar_count;
__device__ volatile unsigned g_bar_gen;

// ---------------- helpers ----------------
__device__ __forceinline__ uint32_t smem_u32(const void* p) {
    uint32_t a;
    asm("{ .reg .u64 t; cvta.to.shared.u64 t, %1; cvt.u32.u64 %0, t; }"
        : "=r"(a) : "l"(p));
    return a;
}
__device__ __forceinline__ void f16split2(float2 f, unsigned int& hi, unsigned int& lo) {
    __half2 h = __float22half2_rn(f);
    hi = *reinterpret_cast<unsigned int*>(&h);
    float2 hf = __half22float2(h);
    __half2 l = __float22half2_rn(make_float2(f.x - hf.x, f.y - hf.y));
    lo = *reinterpret_cast<unsigned int*>(&l);
}
__device__ __forceinline__ void acc_u2(float4& acc, uint2 u) {
    float2 f0 = __half22float2(*reinterpret_cast<__half2*>(&u.x));
    float2 f1 = __half22float2(*reinterpret_cast<__half2*>(&u.y));
    acc.x += f0.x; acc.y += f0.y; acc.z += f1.x; acc.w += f1.y;
}

#define CP_ASYNC16(dst, src, bytes) \
    asm volatile("cp.async.cg.shared.global [%0], [%1], 16, %2;" \
                 :: "r"(dst), "l"(src), "r"(bytes))
#define CP_COMMIT() asm volatile("cp.async.commit_group;" ::: "memory")
#define CP_WAIT1()  asm volatile("cp.async.wait_group 1;" ::: "memory")
#define CP_WAIT0()  asm volatile("cp.async.wait_group 0;" ::: "memory")

#define LDSM4(r, addr)                                                       \
    asm volatile("ldmatrix.sync.aligned.m8n8.x4.shared.b16 {%0,%1,%2,%3}, [%4];" \
                 : "=r"((r)[0]), "=r"((r)[1]), "=r"((r)[2]), "=r"((r)[3])    \
                 : "r"(addr))

#define MMA_F16(d, a, b0, b1)                                               \
    asm volatile("mma.sync.aligned.m16n8k16.row.col.f32.f16.f16.f32 "       \
                 "{%0,%1,%2,%3}, {%4,%5,%6,%7}, {%8,%9}, {%0,%1,%2,%3};"    \
                 : "+f"(d[0]), "+f"(d[1]), "+f"(d[2]), "+f"(d[3])           \
                 : "r"((a)[0]), "r"((a)[1]), "r"((a)[2]), "r"((a)[3]),      \
                   "r"(b0), "r"(b1))

// ---------------- software grid barrier (all blocks resident by construction) ----------------
__device__ __forceinline__ void gbar(int G) {
    __threadfence();              // release my writes (scope gpu -> L1 inval per sm_103a)
    __syncthreads();
    if (threadIdx.x == 0) {
        unsigned gen = g_bar_gen;
        if (atomicAdd(&g_bar_count, 1u) == (unsigned)(G - 1)) {
            atomicExch(&g_bar_count, 0u);
            __threadfence();
            g_bar_gen = gen + 1u;
        } else {
            while (g_bar_gen == gen) {
                asm volatile("nanosleep.u32 %0;" :: "r"(64));
            }
        }
    }
    __syncthreads();
    __threadfence();              // acquire: invalidate L1 before reading peers' data
}

// ---------------- GEMM tile (R11-proven 128x128, cp.async + ldmatrix, 3-pass fp16) ----------------
__device__ __forceinline__ void gemm_tile(
    int tile,
    const unsigned int* __restrict__ Ah, const unsigned int* __restrict__ Al,
    const unsigned int* __restrict__ Bhi, const unsigned int* __restrict__ Blo,
    const float* __restrict__ bl,
    float* __restrict__ hout, unsigned int* __restrict__ Ohi, unsigned int* __restrict__ Olo,
    int writeBf, int writeF32, unsigned char* dynsmem)
{
    const uint32_t sbase = smem_u32(dynsmem);
    const int tid = threadIdx.x;
    const int lane = tid & 31;
    const int wid = tid >> 5;
    const int m0w = (wid >> 1) * 32;
    const int n0w = (wid & 1) * 64;
    const int rowBase = tile * 128;
    const int grp = lane >> 2;
    const int tig = lane & 3;

    const int a_row_off = (lane & 7) + ((lane >> 3) & 1) * 8;
    const int a_k_off   = (lane >> 4) * 4;
    const int b_row_off = (lane & 7) + (lane >> 4) * 8;
    const int b_k_off   = ((lane >> 3) & 1) * 4;

    int arow[2], ac4[2];
#pragma unroll
    for (int i = 0; i < 2; i++) {
        int idx = tid + i * 256;
        arow[i] = idx >> 2;
        ac4[i] = (idx & 3) << 2;
    }

    float acc[2][8][4];
#pragma unroll
    for (int mt = 0; mt < 2; mt++)
#pragma unroll
        for (int nt = 0; nt < 8; nt++)
#pragma unroll
            for (int q = 0; q < 4; q++) acc[mt][nt][q] = 0.0f;

    auto issue = [&](int c, int buf) {
        const uint32_t sb = sbase + buf * SM_BUF;
        const unsigned int* srcHi = (c < 4) ? g_gahi : Ah;
        const unsigned int* srcLo = (c < 4) ? g_galo : Al;
        const int colBase = (c & 3) * 16;
#pragma unroll
        for (int i = 0; i < 2; i++) {
            const unsigned int* bgh = Bhi + arow[i] * 128 + c * 16 + ac4[i];
            const unsigned int* bgl = Blo + arow[i] * 128 + c * 16 + ac4[i];
            CP_ASYNC16(sb + SM_BHI + (arow[i] * B_PITCH + ac4[i]) * 4, bgh, 16);
            CP_ASYNC16(sb + SM_BLO + (arow[i] * B_PITCH + ac4[i]) * 4, bgl, 16);
            int gm = rowBase + arow[i];
            int valid = (gm < N_NODES) ? 16 : 0;
            const unsigned int* agh = srcHi + (size_t)gm * 64 + colBase + ac4[i];
            const unsigned int* agl = srcLo + (size_t)gm * 64 + colBase + ac4[i];
            CP_ASYNC16(sb + SM_AHI + (arow[i] * A_PITCH + ac4[i]) * 4, agh, valid);
            CP_ASYNC16(sb + SM_ALO + (arow[i] * A_PITCH + ac4[i]) * 4, agl, valid);
        }
        CP_COMMIT();
    };

    issue(0, 0);

    for (int c = 0; c < 8; c++) {
        const int buf = c & 1;
        if (c < 7) { issue(c + 1, buf ^ 1); CP_WAIT1(); }
        else CP_WAIT0();
        __syncthreads();

        const uint32_t sb = sbase + buf * SM_BUF;

#pragma unroll
        for (int ks = 0; ks < 2; ks++) {
            const int k2b = ks * 8;
            unsigned int ahi[2][4], alo[2][4];
#pragma unroll
            for (int mt = 0; mt < 2; mt++) {
                uint32_t aaddr = sb + SM_AHI +
                    ((m0w + mt * 16 + a_row_off) * A_PITCH + k2b + a_k_off) * 4;
                LDSM4(ahi[mt], aaddr);
                LDSM4(alo[mt], aaddr + (SM_ALO - SM_AHI));
            }
#pragma unroll
            for (int p = 0; p < 4; p++) {
                unsigned int bh[4], blw[4];
                uint32_t baddr = sb + SM_BHI +
                    ((n0w + p * 16 + b_row_off) * B_PITCH + k2b + b_k_off) * 4;
                LDSM4(bh, baddr);
                LDSM4(blw, baddr + (SM_BLO - SM_BHI));
#pragma unroll
                for (int t = 0; t < 2; t++) {
                    const int nt = p * 2 + t;
#pragma unroll
                    for (int mt = 0; mt < 2; mt++) {
                        MMA_F16(acc[mt][nt], ahi[mt], bh[2 * t], bh[2 * t + 1]);
                        MMA_F16(acc[mt][nt], alo[mt], bh[2 * t], bh[2 * t + 1]);
                        MMA_F16(acc[mt][nt], ahi[mt], blw[2 * t], blw[2 * t + 1]);
                    }
                }
            }
        }
        __syncthreads();
    }

#pragma unroll
    for (int mt = 0; mt < 2; mt++) {
        int gm0 = rowBase + m0w + mt * 16 + grp;
        int gm1 = gm0 + 8;
#pragma unroll
        for (int nt = 0; nt < 8; nt++) {
            int n = n0w + nt * 8 + 2 * tig;
            float2 bb = *reinterpret_cast<const float2*>(bl + n);
            if (gm0 < N_NODES) {
                float2 o;
                o.x = fmaxf(acc[mt][nt][0] + bb.x, 0.0f);
                o.y = fmaxf(acc[mt][nt][1] + bb.y, 0.0f);
                if (writeF32)
                    *reinterpret_cast<float2*>(hout + (size_t)gm0 * HID + n) = o;
                if (writeBf) {
                    unsigned int hi, lo;
                    f16split2(o, hi, lo);
                    Ohi[(size_t)gm0 * 64 + (n >> 1)] = hi;
                    Olo[(size_t)gm0 * 64 + (n >> 1)] = lo;
                }
            }
            if (gm1 < N_NODES) {
                float2 o;
                o.x = fmaxf(acc[mt][nt][2] + bb.x, 0.0f);
                o.y = fmaxf(acc[mt][nt][3] + bb.y, 0.0f);
                if (writeF32)
                    *reinterpret_cast<float2*>(hout + (size_t)gm1 * HID + n) = o;
                if (writeBf) {
                    unsigned int hi, lo;
                    f16split2(o, hi, lo);
                    Ohi[(size_t)gm1 * 64 + (n >> 1)] = hi;
                    Olo[(size_t)gm1 * 64 + (n >> 1)] = lo;
                }
            }
        }
    }
}

// ---------------- the persistent mega-kernel ----------------
__global__ void __launch_bounds__(256, 2) mega_kernel(
    const int* __restrict__ src, const int* __restrict__ dst, int E,
    const float* __restrict__ Wl, const float* __restrict__ Wr,
    const float* __restrict__ x, const float* __restrict__ bl,
    const float* __restrict__ gamma, const float* __restrict__ beta,
    const float* __restrict__ fcW, const float* __restrict__ fcb,
    const int* __restrict__ batch, float* __restrict__ out)
{
    extern __shared__ unsigned char dynsmem[];
    __shared__ int s_a[256];
    __shared__ int s_b[256];
    __shared__ float s_row[HID];

    const int tid = threadIdx.x;
    const int G = gridDim.x;
    const int gid = blockIdx.x * 256 + tid;
    const int gsz = G * 256;

    // ---- P0: zero deg + split weights (B^T hi/lo) + split x (hi/lo) ----
    for (int i = gid; i < N_NODES; i += gsz) g_deg[i] = 0;
    for (int i = gid; i < W_ELEMS + N_NODES * 64; i += gsz) {
        if (i < W_ELEMS) {
            int L = i >> 14;
            int r = i & 16383;
            int n = r >> 7;
            int k2 = r & 127;
            int k = k2 << 1;
            const float* W = (k < 128) ? (Wl + L * 16384 + k * 128)
                                       : (Wr + L * 16384 + (k - 128) * 128);
            unsigned int hi, lo;
            f16split2(make_float2(W[n], W[128 + n]), hi, lo);
            g_Bhi[i] = hi;
            g_Blo[i] = lo;
        } else {
            int j = i - W_ELEMS;
            int row = j >> 6;
            int n2 = j & 63;
            float2 v = *reinterpret_cast<const float2*>(x + (size_t)row * HID + 2 * n2);
            unsigned int hi, lo;
            f16split2(v, hi, lo);
            g_Ah[0][j] = hi;
            g_Al[0][j] = lo;
        }
    }
    gbar(G);

    // ---- P1: degree count ----
    for (int i = gid; i < E; i += gsz) atomicAdd(&g_deg[dst[i]], 1);
    gbar(G);

    // ---- P2: per-chunk blocksums (reduction, no contended atomics) ----
    for (int chunk = blockIdx.x; chunk < SCAN_BLOCKS; chunk += G) {
        int i = chunk * 256 + tid;
        int v = (i < N_NODES) ? g_deg[i] : 0;
        s_a[tid] = v;
        __syncthreads();
        for (int off = 128; off > 0; off >>= 1) {
            if (tid < off) s_a[tid] += s_a[tid + off];
            __syncthreads();
        }
        if (tid == 0) g_blocksum[chunk] = s_a[0];
        __syncthreads();
    }
    gbar(G);

    // ---- P3: low scan with inline top scan (every block redundantly scans blocksums) ----
    {
        int v = (tid < SCAN_BLOCKS) ? g_blocksum[tid] : 0;
        s_b[tid] = v;
        __syncthreads();
        for (int off = 1; off < 256; off <<= 1) {
            int u = (tid >= off) ? s_b[tid - off] : 0;
            __syncthreads();
            s_b[tid] += u;
            __syncthreads();
        }
        for (int chunk = blockIdx.x; chunk < SCAN_BLOCKS; chunk += G) {
            int i = chunk * 256 + tid;
            int v2 = (i < N_NODES) ? g_deg[i] : 0;
            s_a[tid] = v2;
            __syncthreads();
            for (int off = 1; off < 256; off <<= 1) {
                int u = (tid >= off) ? s_a[tid - off] : 0;
                __syncthreads();
                s_a[tid] += u;
                __syncthreads();
            }
            if (i < N_NODES) {
                int excl = (s_b[chunk] - g_blocksum[chunk]) + s_a[tid] - v2;
                g_rowstart[i] = excl;
                g_cursor[i] = excl;
                if (i == N_NODES - 1) g_rowstart[N_NODES] = E;
            }
            __syncthreads();
        }
    }
    gbar(G);

    // ---- P4: CSR fill ----
    for (int i = gid; i < E; i += gsz) {
        int pos = atomicAdd(&g_cursor[dst[i]], 1);
        g_csr[pos] = src[i];
    }
    gbar(G);

    // ---- layers ----
    for (int layer = 0; layer < 3; layer++) {
        const int cur = layer & 1;
        const int nxt = cur ^ 1;
        // gather: warp per node, fp16-hi input, fp16 hi/lo mean output
        {
            const unsigned int* h16 = g_Ah[cur];
            int wInB = tid >> 5;
            int lane = tid & 31;
            for (int node = blockIdx.x * 8 + wInB; node < N_NODES; node += G * 8) {
                int s0 = g_rowstart[node];
                int s1 = g_rowstart[node + 1];
                float4 acc = make_float4(0.f, 0.f, 0.f, 0.f);
                int j = s0;
                for (; j + 8 <= s1; j += 8) {
                    int idx[8];
#pragma unroll
                    for (int q = 0; q < 8; q++) idx[q] = __ldg(&g_csr[j + q]);
                    uint2 v[8];
#pragma unroll
                    for (int q = 0; q < 8; q++)
                        v[q] = *reinterpret_cast<const uint2*>(h16 + (size_t)idx[q] * 64 + lane * 2);
#pragma unroll
                    for (int q = 0; q < 8; q++) acc_u2(acc, v[q]);
                }
                for (; j < s1; j++) {
                    uint2 a = *reinterpret_cast<const uint2*>(
                        h16 + (size_t)__ldg(&g_csr[j]) * 64 + lane * 2);
                    acc_u2(acc, a);
                }
                int deg = s1 - s0;
                float inv = 1.0f / (float)(deg > 0 ? deg : 1);
                acc.x *= inv; acc.y *= inv; acc.z *= inv; acc.w *= inv;
                unsigned int h0, l0, h1, l1;
                f16split2(make_float2(acc.x, acc.y), h0, l0);
                f16split2(make_float2(acc.z, acc.w), h1, l1);
                *reinterpret_cast<uint2*>(g_gahi + (size_t)node * 64 + lane * 2) = make_uint2(h0, h1);
                *reinterpret_cast<uint2*>(g_galo + (size_t)node * 64 + lane * 2) = make_uint2(l0, l1);
            }
        }
        gbar(G);

        // GEMM
        {
            const unsigned int* Ah = g_Ah[cur];
            const unsigned int* Al = g_Al[cur];
            const unsigned int* Bh = g_Bhi + layer * 16384;
            const unsigned int* Bl = g_Blo + layer * 16384;
            const float* blp = bl + layer * HID;
            unsigned int* Oh = g_Ah[nxt];
            unsigned int* Ol = g_Al[nxt];
            int writeBf = (layer < 2) ? 1 : 0;
            int writeF32 = (layer == 2) ? 1 : 0;
            for (int tile = blockIdx.x; tile < M_TILES; tile += G)
                gemm_tile(tile, Ah, Al, Bh, Bl, blp, g_hf32, Oh, Ol,
                          writeBf, writeF32, dynsmem);
        }
        gbar(G);
    }

    // ---- pool: block per graph, atomic-free (batch sorted) ----
    for (int g = blockIdx.x; g < N_GRAPHS; g += G) {
        int lo = 0, hi = N_NODES;
        while (lo < hi) { int mid = (lo + hi) >> 1; if (__ldg(&batch[mid]) < g) lo = mid + 1; else hi = mid; }
        int start = lo;
        hi = N_NODES;
        while (lo < hi) { int mid = (lo + hi) >> 1; if (__ldg(&batch[mid]) <= g) lo = mid + 1; else hi = mid; }
        int end = lo;
        if (tid < HID) {
            float acc = 0.0f;
            for (int r = start; r < end; r++)
                acc += g_hf32[(size_t)r * HID + tid];
            g_pooled[g * HID + tid] = acc;
        }
    }
    gbar(G);

    // ---- batchnorm stats (block 0) ----
    if (blockIdx.x == 0 && tid < HID) {
        float s = 0.0f, s2 = 0.0f;
        for (int g = 0; g < N_GRAPHS; g++) {
            float v = g_pooled[g * HID + tid];
            s += v;
            s2 += v * v;
        }
        float mu = s * (1.0f / N_GRAPHS);
        float var = s2 * (1.0f / N_GRAPHS) - mu * mu;
        float sc = gamma[tid] * rsqrtf(var + BN_EPS);
        g_scale[tid] = sc;
        g_shift[tid] = beta[tid] - mu * sc;
    }
    gbar(G);

    // ---- final FC ----
    for (int g = blockIdx.x; g < N_GRAPHS; g += G) {
        if (tid < HID)
            s_row[tid] = g_pooled[g * HID + tid] * g_scale[tid] + g_shift[tid];
        __syncthreads();
        if (tid < LATENT) {
            float acc = fcb[tid];
#pragma unroll
            for (int c = 0; c < HID; c++)
                acc += s_row[c] * __ldg(&fcW[c * LATENT + tid]);
            out[g * LATENT + tid] = acc;
        }
        __syncthreads();
    }
}

// ---------------- launch ----------------
extern "C" void kernel_launch(void* const* d_in, const int* in_sizes, int n_in,
                              void* d_out, int out_size)
{
    const float* x     = (const float*)d_in[0];
    const int*   ei    = (const int*)d_in[1];
    const int*   batch = (const int*)d_in[2];
    const float* Wl    = (const float*)d_in[3];
    const float* bl    = (const float*)d_in[4];
    const float* Wr    = (const float*)d_in[5];
    const float* gamma = (const float*)d_in[6];
    const float* beta  = (const float*)d_in[7];
    const float* fcW   = (const float*)d_in[8];
    const float* fcb   = (const float*)d_in[9];
    float* out = (float*)d_out;

    const int E = in_sizes[1] / 2;
    const int* src = ei;
    const int* dst = ei + E;

    cudaFuncSetAttribute(mega_kernel,
                         cudaFuncAttributeMaxDynamicSharedMemorySize, SM_TOTAL);

    int dev = 0;
    cudaGetDevice(&dev);
    int sms = 0;
    cudaDeviceGetAttribute(&sms, cudaDevAttrMultiProcessorCount, dev);
    if (sms <= 0) sms = 148;
    int occ = 0;
    cudaOccupancyMaxActiveBlocksPerMultiprocessor(&occ, mega_kernel, 256, SM_TOTAL);
    if (occ < 1) occ = 1;
    if (occ > 2) occ = 2;
    const int G = sms * occ;

    mega_kernel<<<G, 256, SM_TOTAL>>>(src, dst, E, Wl, Wr, x, bl,
                                      gamma, beta, fcW, fcb, batch, out);
}